// round 2
// baseline (speedup 1.0000x reference)
#include <cuda_runtime.h>
#include <cstdint>

// NRI MLPDecoder, pred_steps=1.
// B=16, N=30, T=50 (49 output steps), D=4, K=4, H=M=NH=128, E=870 (=30*29).
// One CTA handles one (b, n, chunk-of-7 timesteps). 128 threads.
//
// Edge e for receiver n: e = n*29 + idx, sender = idx<n ? idx : idx+1.
// agg[b,t,n,:] = sum over those 29 edges of sum_k relu(relu(pre@W1k+b1k)@W2k+b2k)*rt[b,e,k]
// out[b,n,t,:] = x + MLP([x, agg])

#define THREADS 128
#define NB 16
#define NN 30
#define TFULL 50
#define TOUT 49
#define TPC 7          // timesteps per CTA
#define NCH 7          // chunks (49/7)
#define GRID (NB*NN*NCH)

typedef unsigned long long ull;

__device__ __forceinline__ ull pk2(float a, float b){
  ull r; asm("mov.b64 %0, {%1,%2};" : "=l"(r) : "f"(a), "f"(b)); return r;
}
__device__ __forceinline__ void upk2(float&a, float&b, ull v){
  asm("mov.b64 {%0,%1}, %2;" : "=f"(a), "=f"(b) : "l"(v));
}
__device__ __forceinline__ void ffma2(ull &d, ull a, ull b){
  asm("fma.rn.f32x2 %0, %1, %2, %3;" : "=l"(d) : "l"(a), "l"(b), "l"(d));
}

// shared memory layout (float offsets)
#define OFF_W1   0        // [4][8][128] = 4096
#define OFF_B1   4096     // [4][128]
#define OFF_B2   4608     // [4][128]
#define OFF_W2   5120     // [128][128] (one k at a time) = 16384
#define OFF_H1T  21504    // [128 c][32 e] = 4096 (also reused as scratch for node MLP)
#define OFF_PRE  25600    // [7 tt][32 e][9 (8 + pad)] = 2016
#define OFF_RT   27616    // [32 e][4 k] = 128
#define OFF_OB1  27744    // 128
#define OFF_OB2  27872    // 128
#define OFF_OB3  28000    // 4
#define SMEM_FLOATS 28032
#define SMEM_BYTES (SMEM_FLOATS*4)

extern __shared__ float smem[];

__global__ __launch_bounds__(THREADS, 2)
void nri_dec_kernel(
    const float* __restrict__ inputs,    // [16,30,50,4]  (B,N,T,D!)
    const float* __restrict__ rel_type,  // [16,870,4]
    const float* __restrict__ W1,        // [4,8,128]
    const float* __restrict__ b1,        // [4,128]
    const float* __restrict__ W2,        // [4,128,128]
    const float* __restrict__ b2,        // [4,128]
    const float* __restrict__ oW1,       // [132,128]
    const float* __restrict__ ob1,       // [128]
    const float* __restrict__ oW2,       // [128,128]
    const float* __restrict__ ob2,       // [128]
    const float* __restrict__ oW3,       // [128,4]
    const float* __restrict__ ob3,       // [4]
    float* __restrict__ out)             // [16,30,49,4]
{
  const int tid = threadIdx.x;
  const int bid = blockIdx.x;
  const int tc = bid % NCH;
  const int n  = (bid / NCH) % NN;
  const int b  = bid / (NCH * NN);

  float* W1s  = smem + OFF_W1;
  float* b1s  = smem + OFF_B1;
  float* b2s  = smem + OFF_B2;
  float* W2s  = smem + OFF_W2;
  float* h1T  = smem + OFF_H1T;
  float* pres = smem + OFF_PRE;
  float* rts  = smem + OFF_RT;
  float* ob1s = smem + OFF_OB1;
  float* ob2s = smem + OFF_OB2;
  float* ob3s = smem + OFF_OB3;

  // ---- stage constants ----
  #pragma unroll
  for (int r = 0; r < 32; r++) W1s[tid + 128*r] = W1[tid + 128*r];
  #pragma unroll
  for (int r = 0; r < 4; r++){
    b1s[tid + 128*r] = b1[tid + 128*r];
    b2s[tid + 128*r] = b2[tid + 128*r];
  }
  ob1s[tid] = ob1[tid];
  ob2s[tid] = ob2[tid];
  if (tid < 4) ob3s[tid] = ob3[tid];

  { // rel_type for this (b, n): 29 real edges, pad to 32 with 0
    int e = tid >> 2, kk = tid & 3;
    rts[tid] = (e < 29) ? rel_type[(b*870 + n*29 + e)*4 + kk] : 0.f;
  }

  // ---- gather pre_msg for all 7 timesteps: pres[tt][e][0..7] = [x(recv=n), x(send)]
  for (int row = tid; row < TPC*32; row += THREADS){
    int tt = row >> 5, e = row & 31;
    float* pr = pres + row*9;
    if (e < 29){
      int t = tc*TPC + tt;
      int s = (e < n) ? e : e + 1;
      const float4 rv = *(const float4*)&inputs[((b*NN + n)*TFULL + t)*4];
      const float4 sv = *(const float4*)&inputs[((b*NN + s)*TFULL + t)*4];
      pr[0]=rv.x; pr[1]=rv.y; pr[2]=rv.z; pr[3]=rv.w;
      pr[4]=sv.x; pr[5]=sv.y; pr[6]=sv.z; pr[7]=sv.w;
    } else {
      #pragma unroll
      for (int d = 0; d < 8; d++) pr[d] = 0.f;
    }
  }

  // per-thread aggregation accumulators: agg partial for 4 features x 7 timesteps
  float aggp[TPC][4];
  #pragma unroll
  for (int tt = 0; tt < TPC; tt++){
    aggp[tt][0]=0.f; aggp[tt][1]=0.f; aggp[tt][2]=0.f; aggp[tt][3]=0.f;
  }

  const int fi = tid & 31;       // feature tile: f0 = 4*fi
  const int ei = tid >> 5;       // edge tile:    e0 = 8*ei
  const int f0 = fi * 4;
  const int e0 = ei * 8;

  __syncthreads();

  // ================= edge MLP: k outer (W2 staged once per k), t inner ==========
  for (int k = 0; k < 4; k++){
    { // stage W2[k] -> smem [c][f]
      const float4* w2g = (const float4*)(W2 + k*16384);
      float4* w2s = (float4*)W2s;
      #pragma unroll
      for (int r = 0; r < 32; r++) w2s[tid + 128*r] = w2g[tid + 128*r];
    }
    __syncthreads();

    #pragma unroll
    for (int tt = 0; tt < TPC; tt++){
      // ---- layer 1: h1T[c][e] = relu(b1 + pre[e] . W1[:,c]) ----
      {
        int e = tid & 31, w = tid >> 5;   // warp lanes sweep e (coalesced h1T writes)
        const float* pr = pres + (tt*32 + e)*9;
        float p0=pr[0],p1=pr[1],p2=pr[2],p3=pr[3],p4=pr[4],p5=pr[5],p6=pr[6],p7=pr[7];
        const float* w1k = W1s + k*1024;
        const float* b1k = b1s + k*128;
        #pragma unroll 4
        for (int r = 0; r < 32; r++){
          int c = w + 4*r;
          float a = b1k[c]
            + p0*w1k[c]       + p1*w1k[128 + c] + p2*w1k[256 + c] + p3*w1k[384 + c]
            + p4*w1k[512 + c] + p5*w1k[640 + c] + p6*w1k[768 + c] + p7*w1k[896 + c];
          h1T[c*32 + e] = fmaxf(a, 0.f);
        }
      }
      __syncthreads();

      // ---- layer 2: 32x128 GEMM, 8e x 4f register tile, packed f32x2 FMAs ----
      ull acc[8][2];
      {
        const float4 bb = *(const float4*)&b2s[k*128 + f0];
        const ull bi0 = pk2(bb.x, bb.y), bi1 = pk2(bb.z, bb.w);
        #pragma unroll
        for (int i = 0; i < 8; i++){ acc[i][0] = bi0; acc[i][1] = bi1; }
      }
      #pragma unroll 4
      for (int c = 0; c < 128; c++){
        const float4 hA = *(const float4*)&h1T[c*32 + e0];       // broadcast in warp
        const float4 hB = *(const float4*)&h1T[c*32 + e0 + 4];
        const float4 w4 = *(const float4*)&W2s[c*128 + f0];      // conflict-free
        const ull w01 = pk2(w4.x, w4.y), w23 = pk2(w4.z, w4.w);
        const float hv[8] = {hA.x,hA.y,hA.z,hA.w,hB.x,hB.y,hB.z,hB.w};
        #pragma unroll
        for (int i = 0; i < 8; i++){
          const ull hp = pk2(hv[i], hv[i]);
          ffma2(acc[i][0], hp, w01);
          ffma2(acc[i][1], hp, w23);
        }
      }
      // epilogue: relu, weight by rel_type, accumulate into per-thread agg partials
      #pragma unroll
      for (int i = 0; i < 8; i++){
        const float r = rts[(e0 + i)*4 + k];
        float v0,v1,v2,v3;
        upk2(v0, v1, acc[i][0]);
        upk2(v2, v3, acc[i][1]);
        aggp[tt][0] += fmaxf(v0, 0.f) * r;
        aggp[tt][1] += fmaxf(v1, 0.f) * r;
        aggp[tt][2] += fmaxf(v2, 0.f) * r;
        aggp[tt][3] += fmaxf(v3, 0.f) * r;
      }
      __syncthreads();   // protect h1T (next tt) / W2s (next k)
    }
  }

  // ================= node MLP (reuse h1T region as scratch) =====================
  float* red  = h1T;          // [4][128]
  float* augs = h1T + 1024;   // [132]
  float* hs   = h1T + 1216;   // [128]
  float* h2s  = h1T + 1408;   // [128]

  #pragma unroll
  for (int tt = 0; tt < TPC; tt++){
    *(float4*)&red[ei*128 + f0] =
        make_float4(aggp[tt][0], aggp[tt][1], aggp[tt][2], aggp[tt][3]);
    __syncthreads();
    {
      float s = red[tid] + red[128 + tid] + red[256 + tid] + red[384 + tid];
      augs[4 + tid] = s;
      if (tid < 4) augs[tid] = pres[(tt*32)*9 + tid];   // x[b,t,n,:] = recv of edge 0
    }
    __syncthreads();
    { // h = relu(aug @ oW1 + ob1)
      float a = ob1s[tid];
      #pragma unroll 4
      for (int i = 0; i < 132; i++) a += augs[i] * oW1[i*128 + tid];
      hs[tid] = fmaxf(a, 0.f);
    }
    __syncthreads();
    { // h2 = relu(h @ oW2 + ob2)
      float a = ob2s[tid];
      #pragma unroll 4
      for (int i = 0; i < 128; i++) a += hs[i] * oW2[i*128 + tid];
      h2s[tid] = fmaxf(a, 0.f);
    }
    __syncthreads();
    if (tid < 4){ // out = x + h2 @ oW3 + ob3
      float a = ob3s[tid];
      #pragma unroll 4
      for (int j = 0; j < 128; j++) a += h2s[j] * oW3[j*4 + tid];
      const int t = tc*TPC + tt;
      out[((b*NN + n)*TOUT + t)*4 + tid] = pres[tt*32*9 + tid] + a;
    }
    __syncthreads();
  }
}

extern "C" void kernel_launch(void* const* d_in, const int* in_sizes, int n_in,
                              void* d_out, int out_size) {
  (void)in_sizes; (void)n_in; (void)out_size;
  const float* inputs   = (const float*)d_in[0];
  const float* rel_type = (const float*)d_in[1];
  // d_in[2] rel_rec, d_in[3] rel_send: implied by index math, unused
  const float* W1  = (const float*)d_in[4];
  const float* b1  = (const float*)d_in[5];
  const float* W2  = (const float*)d_in[6];
  const float* b2  = (const float*)d_in[7];
  const float* oW1 = (const float*)d_in[8];
  const float* ob1 = (const float*)d_in[9];
  const float* oW2 = (const float*)d_in[10];
  const float* ob2 = (const float*)d_in[11];
  const float* oW3 = (const float*)d_in[12];
  const float* ob3 = (const float*)d_in[13];
  float* out = (float*)d_out;

  cudaFuncSetAttribute(nri_dec_kernel,
                       cudaFuncAttributeMaxDynamicSharedMemorySize, SMEM_BYTES);
  nri_dec_kernel<<<GRID, THREADS, SMEM_BYTES>>>(
      inputs, rel_type, W1, b1, W2, b2, oW1, ob1, oW2, ob2, oW3, ob3, out);
}

// round 4
// speedup vs baseline: 3.0372x; 3.0372x over previous
#include <cuda_runtime.h>
#include <cuda_fp16.h>
#include <cstdint>

// NRI MLPDecoder via legacy tensor path (mma.sync.m16n8k16.f16, fp32 accum).
// B=16, N=30, T=50 (49 out), D=4, K=4, H=M=NH=128, E=870 (pad 896 = 7x128).
// One CTA = one (b,t), 256 threads, grid 784.
// Per tile (128 edges) per relation k:
//   A[e][c] = relu(pre@W1k+b1k) * rt[e][k]        (SIMT f32x2 -> fp16 smem)
//   z       = A @ W2k  (+ rt*b2 init)             (mma.sync m16n8k16, HMMA)
//   accP   += relu(z)                             (fp32 regs across k)
// then fp16 msgs -> receiver-contiguous segmented scan -> agg -> SIMT node MLP.

typedef unsigned long long ull;

#define NB 16
#define NN 30
#define TFULL 50
#define TOUT 49
#define EDGES 870
#define NTILE 7
#define THREADS 256
#define GRID (NB*TOUT)

// ---------------- smem byte offsets ----------------
#define SA    0          // A fp16 [128][136] = 34816  (alias: msgs fp16 [128][132])
#define SB    34816      // B fp16 4x[128][136] = 139264 (alias phase-B scratch)
#define SW1   174080     // W1 f32 [4][8][128] = 16384  
#define SB1   190464     // b1 f32 [4][128] = 2048
#define SB2   192512     // b2 f32 [4][128] = 2048
#define SPRE  194560     // pre f32 [128][9] = 4608
#define SXS   199168     // x f32 [32][4] = 512
#define SAGG  199680     // agg f32 [30][128] = 15360
#define SRT   215040     // rt f32 [896][4] = 14336
#define SOB   229376     // ob1 512 + ob2 512 + ob3 16 = 1040
#define SMEM_BYTES 230416

// phase-B aliases (inside SB region)
#define PB_AUG  (SB)            // [30][132] f32 = 15840
#define PB_H    (SB + 16384)    // [30][128] f32
#define PB_H2   (SB + 32768)    // [30][129] f32
#define PB_P0   (SB + 49152)    // [30][128] f32
#define PB_P1   (SB + 65536)    // [30][128] f32

__device__ __align__(16) __half g_W2h[4*128*136];  // W2^T fp16: [k][m][c_pad136]

// ---------------- helpers ----------------
__device__ __forceinline__ ull pk2(float a, float b){
  ull r; asm("mov.b64 %0, {%1,%2};" : "=l"(r) : "f"(a), "f"(b)); return r;
}
__device__ __forceinline__ void upk2(float&a, float&b, ull v){
  asm("mov.b64 {%0,%1}, %2;" : "=f"(a), "=f"(b) : "l"(v));
}
__device__ __forceinline__ void ffma2(ull &d, ull a, ull b){
  asm("fma.rn.f32x2 %0, %1, %2, %3;" : "=l"(d) : "l"(a), "l"(b), "l"(d));
}
__device__ __forceinline__ uint32_t smem_u32(const void* p){
  uint32_t a; asm("{ .reg .u64 t; cvta.to.shared.u64 t, %1; cvt.u32.u64 %0, t; }" : "=r"(a) : "l"(p));
  return a;
}
__device__ __forceinline__ void cp16(uint32_t dst, const void* src){
  asm volatile("cp.async.ca.shared.global [%0], [%1], 16;" :: "r"(dst), "l"(src));
}
__device__ __forceinline__ void cp_commit(){ asm volatile("cp.async.commit_group;" ::: "memory"); }
__device__ __forceinline__ void cp_wait0(){ asm volatile("cp.async.wait_group 0;" ::: "memory"); }

__device__ __forceinline__ void mma16816(float* c,
    uint32_t a0, uint32_t a1, uint32_t a2, uint32_t a3,
    uint32_t b0, uint32_t b1){
  asm volatile("mma.sync.aligned.m16n8k16.row.col.f32.f16.f16.f32 "
    "{%0,%1,%2,%3}, {%4,%5,%6,%7}, {%8,%9}, {%0,%1,%2,%3};"
    : "+f"(c[0]), "+f"(c[1]), "+f"(c[2]), "+f"(c[3])
    : "r"(a0), "r"(a1), "r"(a2), "r"(a3), "r"(b0), "r"(b1));
}

// ---------------- prep: W2^T -> fp16, padded stride 136 ----------------
__global__ void prep_w2(const float* __restrict__ W2){
  int idx = blockIdx.x * blockDim.x + threadIdx.x;
  if (idx >= 4*128*128) return;
  int k = idx >> 14, rem = idx & 16383;
  int m = rem >> 7, c = rem & 127;
  // B[k_dim=c][n=m] = W2[k][c][m]; store Bs[m][c] so (c,c+1) are contiguous
  g_W2h[(k*128 + m)*136 + c] = __float2half(W2[(k*128 + c)*128 + m]);
}

// ---------------- main ----------------
extern __shared__ __align__(16) char smc[];

__global__ __launch_bounds__(THREADS, 1)
void nri_mma_kernel(
    const float* __restrict__ inputs,    // [16,30,50,4]
    const float* __restrict__ rel_type,  // [16,870,4]
    const float* __restrict__ W1,        // [4,8,128]
    const float* __restrict__ b1,        // [4,128]
    const float* __restrict__ b2,        // [4,128]
    const float* __restrict__ oW1,       // [132,128]
    const float* __restrict__ ob1,
    const float* __restrict__ oW2,       // [128,128]
    const float* __restrict__ ob2,
    const float* __restrict__ oW3,       // [128,4]
    const float* __restrict__ ob3,
    float* __restrict__ out)             // [16,30,49,4]
{
  const int tid  = threadIdx.x;
  const int lane = tid & 31;
  const int g    = lane >> 2;      // groupID
  const int tg   = lane & 3;       // thread in group
  const int wid  = tid >> 5;
  const int wr   = wid >> 1;       // warp row (0..3): 32 edges
  const int wc   = wid & 1;        // warp col (0..1): 64 features
  const int b = blockIdx.x / TOUT;
  const int t = blockIdx.x % TOUT;

  const uint32_t sbase = smem_u32(smc);
  float* W1s  = (float*)(smc + SW1);
  float* b1s  = (float*)(smc + SB1);
  float* b2s  = (float*)(smc + SB2);
  float* PRE  = (float*)(smc + SPRE);
  float* XS   = (float*)(smc + SXS);
  float* AGG  = (float*)(smc + SAGG);
  float* RTs  = (float*)(smc + SRT);
  float* ob1s = (float*)(smc + SOB);
  float* ob2s = (float*)(smc + SOB + 512);
  float* ob3s = (float*)(smc + SOB + 1024);

  // ---- prologue: async-stage all weights ----
  for (int i = tid; i < 8704; i += THREADS)          // 4x W2^T fp16 (139264B)
    cp16(sbase + SB + i*16, (const char*)g_W2h + i*16);
  for (int i = tid; i < 1024; i += THREADS)          // W1 f32
    cp16(sbase + SW1 + i*16, (const char*)W1 + i*16);
  for (int i = tid; i < 128; i += THREADS){
    cp16(sbase + SB1 + i*16, (const char*)b1 + i*16);
    cp16(sbase + SB2 + i*16, (const char*)b2 + i*16);
  }
  cp_commit();
  for (int i = tid; i < 3584; i += THREADS)
    RTs[i] = (i < EDGES*4) ? rel_type[b*EDGES*4 + i] : 0.f;
  if (tid < 120){
    int n = tid >> 2, d = tid & 3;
    XS[tid] = inputs[((b*NN + n)*TFULL + t)*4 + d];
  }
  if (tid < 128) ob1s[tid] = ob1[tid];
  else           ob2s[tid-128] = ob2[tid-128];
  if (tid < 4) ob3s[tid] = ob3[tid];
  cp_wait0();
  __syncthreads();

  // segmented scan state (thread tid<128 owns feature f=tid)
  int cur_node = 0;
  float cur_sum = 0.f;

  // ================= edge tiles =================
  for (int m = 0; m < NTILE; m++){
    // ---- gather pre (thread = edge) ----
    if (tid < 128){
      int ge = m*128 + tid;
      float* pr = PRE + tid*9;
      if (ge < EDGES){
        int n = (ge*565) >> 14;               // ge/29 exact for ge<870
        int idx = ge - n*29;
        int s = idx + (idx >= n ? 1 : 0);
        const float4 rv = *(const float4*)(XS + n*4);
        const float4 sv = *(const float4*)(XS + s*4);
        pr[0]=rv.x; pr[1]=rv.y; pr[2]=rv.z; pr[3]=rv.w;
        pr[4]=sv.x; pr[5]=sv.y; pr[6]=sv.z; pr[7]=sv.w;
      } else {
        #pragma unroll
        for (int i = 0; i < 8; i++) pr[i] = 0.f;
      }
    }
    __syncthreads();

    float accP[2][8][4];
    #pragma unroll
    for (int i = 0; i < 2; i++)
      #pragma unroll
      for (int j = 0; j < 8; j++)
        #pragma unroll
        for (int r = 0; r < 4; r++) accP[i][j][r] = 0.f;

    for (int k = 0; k < 4; k++){
      // ---- layer 1 (f32x2) -> A fp16, rt folded into rows ----
      {
        const int e1 = tid >> 1;
        const int c00 = (tid & 1) * 64;
        const float rte = RTs[(m*128 + e1)*4 + k];
        ull hp[8];
        #pragma unroll
        for (int i = 0; i < 8; i++){ float p = PRE[e1*9 + i]; hp[i] = pk2(p, p); }
        const float* w1k = W1s + k*1024;
        const float* b1k = b1s + k*128;
        char* Arow = smc + SA + e1*272;
        #pragma unroll
        for (int cc = 0; cc < 64; cc += 4){
          const int c = c00 + cc;
          const float4 b4 = *(const float4*)(b1k + c);
          ull a0 = pk2(b4.x, b4.y), a1 = pk2(b4.z, b4.w);
          #pragma unroll
          for (int i = 0; i < 8; i++){
            const float4 w = *(const float4*)(w1k + i*128 + c);
            ffma2(a0, hp[i], pk2(w.x, w.y));
            ffma2(a1, hp[i], pk2(w.z, w.w));
          }
          float v0,v1,v2,v3; upk2(v0,v1,a0); upk2(v2,v3,a1);
          __half2 h01 = __floats2half2_rn(fmaxf(v0,0.f)*rte, fmaxf(v1,0.f)*rte);
          __half2 h23 = __floats2half2_rn(fmaxf(v2,0.f)*rte, fmaxf(v3,0.f)*rte);
          uint2 st; st.x = *(uint32_t*)&h01; st.y = *(uint32_t*)&h23;
          *(uint2*)(Arow + c*2) = st;
        }
      }
      __syncthreads();

      // ---- z init = rt * b2 ----
      float z[2][8][4];
      {
        float rt2[4];
        #pragma unroll
        for (int i = 0; i < 2; i++)
          #pragma unroll
          for (int h = 0; h < 2; h++)
            rt2[i*2+h] = RTs[(m*128 + wr*32 + i*16 + h*8 + g)*4 + k];
        #pragma unroll
        for (int j = 0; j < 8; j++){
          const float2 bp = *(const float2*)(b2s + k*128 + wc*64 + j*8 + tg*2);
          #pragma unroll
          for (int i = 0; i < 2; i++){
            z[i][j][0] = rt2[i*2+0]*bp.x; z[i][j][1] = rt2[i*2+0]*bp.y;
            z[i][j][2] = rt2[i*2+1]*bp.x; z[i][j][3] = rt2[i*2+1]*bp.y;
          }
        }
      }
      // ---- mma mainloop: 8 k-steps of 16 ----
      {
        const char* Af = smc + SA + (wr*32 + g)*272 + tg*4;
        const char* Bf = smc + SB + k*34816 + (wc*64 + g)*272 + tg*4;
        #pragma unroll
        for (int ks = 0; ks < 8; ks++){
          uint32_t a[2][4];
          #pragma unroll
          for (int i = 0; i < 2; i++){
            const char* ab = Af + i*(16*272) + ks*32;
            a[i][0] = *(const uint32_t*)(ab);
            a[i][1] = *(const uint32_t*)(ab + 8*272);
            a[i][2] = *(const uint32_t*)(ab + 16);
            a[i][3] = *(const uint32_t*)(ab + 8*272 + 16);
          }
          #pragma unroll
          for (int j = 0; j < 8; j++){
            const char* bb = Bf + j*(8*272) + ks*32;
            const uint32_t b0 = *(const uint32_t*)(bb);
            const uint32_t b1r = *(const uint32_t*)(bb + 16);
            mma16816(z[0][j], a[0][0],a[0][1],a[0][2],a[0][3], b0, b1r);
            mma16816(z[1][j], a[1][0],a[1][1],a[1][2],a[1][3], b0, b1r);
          }
        }
      }
      // ---- accP += relu(z) ----
      #pragma unroll
      for (int i = 0; i < 2; i++)
        #pragma unroll
        for (int j = 0; j < 8; j++)
          #pragma unroll
          for (int r = 0; r < 4; r++)
            accP[i][j][r] += fmaxf(z[i][j][r], 0.f);
      __syncthreads();   // A reusable next k
    }

    // ---- store msgs fp16 [128][132] (alias A region) ----
    #pragma unroll
    for (int i = 0; i < 2; i++)
      #pragma unroll
      for (int h = 0; h < 2; h++){
        const int e = wr*32 + i*16 + h*8 + g;
        char* mrow = smc + SA + e*264;
        #pragma unroll
        for (int j = 0; j < 8; j++){
          const int f = wc*64 + j*8 + tg*2;
          __half2 hv = (h == 0)
            ? __floats2half2_rn(accP[i][j][0], accP[i][j][1])
            : __floats2half2_rn(accP[i][j][2], accP[i][j][3]);
          *(uint32_t*)(mrow + f*2) = *(uint32_t*)&hv;
        }
      }
    __syncthreads();

    // ---- segmented scan over receiver-contiguous edges ----
    if (tid < 128){
      const __half* msgs = (const __half*)(smc + SA);
      #pragma unroll 4
      for (int el = 0; el < 128; el++){
        const int ge = m*128 + el;
        const int n = (ge*565) >> 14;
        if (n != cur_node){
          if (cur_node < NN) AGG[cur_node*128 + tid] = cur_sum;
          cur_sum = 0.f; cur_node = n;
        }
        cur_sum += __half2float(msgs[el*132 + tid]);
      }
    }
    __syncthreads();
  }

  // ================= node MLP (weight-stationary, i-split halves) =========
  float* AUG = (float*)(smc + PB_AUG);   // [30][132]
  float* H   = (float*)(smc + PB_H);     // [30][128]
  float* H2  = (float*)(smc + PB_H2);    // [30][129]
  float* P0  = (float*)(smc + PB_P0);
  float* P1  = (float*)(smc + PB_P1);

  for (int idx = tid; idx < NN*132; idx += THREADS){
    int n = idx / 132, i = idx - n*132;
    AUG[idx] = (i < 4) ? XS[n*4 + i] : AGG[n*128 + (i - 4)];
  }
  __syncthreads();
  { // layer 1: P[half] = aug @ oW1 (i-range split)
    const int f = tid & 127, half = tid >> 7;
    const int i0 = half ? 66 : 0, i1 = half ? 132 : 66;
    float acc[NN];
    #pragma unroll
    for (int n = 0; n < NN; n++) acc[n] = 0.f;
    for (int i = i0; i < i1; i++){
      const float w = oW1[i*128 + f];
      #pragma unroll
      for (int n = 0; n < NN; n++) acc[n] += AUG[n*132 + i] * w;
    }
    float* P = half ? P1 : P0;
    #pragma unroll
    for (int n = 0; n < NN; n++) P[n*128 + f] = acc[n];
  }
  __syncthreads();
  for (int idx = tid; idx < NN*128; idx += THREADS)
    H[idx] = fmaxf(P0[idx] + P1[idx] + ob1s[idx & 127], 0.f);
  __syncthreads();
  { // layer 2
    const int f = tid & 127, half = tid >> 7;
    const int i0 = half ? 64 : 0, i1 = half ? 128 : 64;
    float acc[NN];
    #pragma unroll
    for (int n = 0; n < NN; n++) acc[n] = 0.f;
    for (int i = i0; i < i1; i++){
      const float w = oW2[i*128 + f];
      #pragma unroll
      for (int n = 0; n < NN; n++) acc[n] += H[n*128 + i] * w;
    }
    float* P = half ? P1 : P0;
    #pragma unroll
    for (int n = 0; n < NN; n++) P[n*128 + f] = acc[n];
  }
  __syncthreads();
  for (int idx = tid; idx < NN*128; idx += THREADS){
    int n = idx >> 7, f = idx & 127;
    H2[n*129 + f] = fmaxf(P0[idx] + P1[idx] + ob2s[f], 0.f);
  }
  __syncthreads();
  if (tid < NN*4){ // layer 3 + residual
    const int n = tid >> 2, d = tid & 3;
    float a = ob3s[d];
    #pragma unroll 8
    for (int j = 0; j < 128; j++) a += H2[n*129 + j] * oW3[j*4 + d];
    out[((b*NN + n)*TOUT + t)*4 + d] = XS[n*4 + d] + a;
  }
}

extern "C" void kernel_launch(void* const* d_in, const int* in_sizes, int n_in,
                              void* d_out, int out_size) {
  (void)in_sizes; (void)n_in; (void)out_size;
  const float* inputs   = (const float*)d_in[0];
  const float* rel_type = (const float*)d_in[1];
  const float* W1  = (const float*)d_in[4];
  const float* b1  = (const float*)d_in[5];
  const float* W2  = (const float*)d_in[6];
  const float* b2  = (const float*)d_in[7];
  const float* oW1 = (const float*)d_in[8];
  const float* ob1 = (const float*)d_in[9];
  const float* oW2 = (const float*)d_in[10];
  const float* ob2 = (const float*)d_in[11];
  const float* oW3 = (const float*)d_in[12];
  const float* ob3 = (const float*)d_in[13];
  float* out = (float*)d_out;

  prep_w2<<<256, 256>>>(W2);

  cudaFuncSetAttribute(nri_mma_kernel,
                       cudaFuncAttributeMaxDynamicSharedMemorySize, SMEM_BYTES);
  nri_mma_kernel<<<GRID, THREADS, SMEM_BYTES>>>(
      inputs, rel_type, W1, b1, b2, oW1, ob1, oW2, ob2, oW3, ob3, out);
}

// round 8
// speedup vs baseline: 3.5922x; 1.1827x over previous
#include <cuda_runtime.h>
#include <cuda_fp16.h>
#include <cstdint>

// NRI MLPDecoder via mma.sync.m16n8k16 (HMMA, fp32 accum), k-outer / 2 CTAs/SM.
// B=16, N=30, T=50 (49 out), D=4, K=4, H=M=NH=128, E=870 (pad 896 = 7x128).
// One CTA = one (b,t), 256 threads, grid 784.
// k outer (W2k staged once per k), 7 edge-tiles inner:
//   A[e][c] = relu(pre@W1k+b1k) * rt[e][k]     (SIMT f32x2 -> fp16 smem)
//   z       = A @ W2k (+ rt*b2 init)           (mma.sync, HMMA)
//   msgs    = relu(z) fp16 -> per-node partial sums -> AGG +=
// then SIMT node MLP.

typedef unsigned long long ull;

#define NB 16
#define NN 30
#define TFULL 50
#define TOUT 49
#define EDGES 870
#define NTILE 7
#define THREADS 256
#define GRID (NB*TOUT)

// ---------------- smem byte offsets ----------------
#define SA    0          // A fp16 [128][136] = 34816 (alias: msgs fp16 [128][132])
#define SW2   34816      // W2k fp16 [128][136] = 34816 (one k at a time)
#define SW1   69632      // W1 f32 [4][8][128] = 16384
#define SB1   86016      // b1 f32 [4][128] = 2048
#define SB2   88064      // b2 f32 [4][128] = 2048
#define SRTK  90112      // rt_k f32 [896] = 3584
#define SAGG  93696      // agg f32 [30][128] = 15360
#define SXS   109184     // x f32 [32][4] = 512
#define SOB   109696     // ob1 512 + ob2 512 + ob3 16
#define SMEM_BYTES 110848

// phase-B aliases
#define PB_AUG  (SA)             // [30][132] f32 = 15840
#define PB_H    (SA + 16384)     // [30][128] f32 = 15360
#define PB_P0   (SW2)            // [30][128] f32
#define PB_P1   (SW2 + 16384)    // [30][128] f32
#define PB_H2   (SAGG)           // [30][129] f32 = 15480 (spills into SRTK-dead? no: AGG+RTK dead by then; fits before SXS)

__device__ __align__(16) __half g_W2h[4*128*136];  // W2^T fp16: [k][m][c_pad136]

// ---------------- helpers ----------------
__device__ __forceinline__ ull pk2(float a, float b){
  ull r; asm("mov.b64 %0, {%1,%2};" : "=l"(r) : "f"(a), "f"(b)); return r;
}
__device__ __forceinline__ void upk2(float&a, float&b, ull v){
  asm("mov.b64 {%0,%1}, %2;" : "=f"(a), "=f"(b) : "l"(v));
}
__device__ __forceinline__ void ffma2(ull &d, ull a, ull b){
  asm("fma.rn.f32x2 %0, %1, %2, %3;" : "=l"(d) : "l"(a), "l"(b), "l"(d));
}
__device__ __forceinline__ uint32_t smem_u32(const void* p){
  uint32_t a; asm("{ .reg .u64 t; cvta.to.shared.u64 t, %1; cvt.u32.u64 %0, t; }" : "=r"(a) : "l"(p));
  return a;
}
__device__ __forceinline__ void cp16(uint32_t dst, const void* src){
  asm volatile("cp.async.ca.shared.global [%0], [%1], 16;" :: "r"(dst), "l"(src));
}
__device__ __forceinline__ void cp_commit(){ asm volatile("cp.async.commit_group;" ::: "memory"); }
__device__ __forceinline__ void cp_wait0(){ asm volatile("cp.async.wait_group 0;" ::: "memory"); }

__device__ __forceinline__ void mma16816(float* c,
    uint32_t a0, uint32_t a1, uint32_t a2, uint32_t a3,
    uint32_t b0, uint32_t b1){
  asm volatile("mma.sync.aligned.m16n8k16.row.col.f32.f16.f16.f32 "
    "{%0,%1,%2,%3}, {%4,%5,%6,%7}, {%8,%9}, {%0,%1,%2,%3};"
    : "+f"(c[0]), "+f"(c[1]), "+f"(c[2]), "+f"(c[3])
    : "r"(a0), "r"(a1), "r"(a2), "r"(a3), "r"(b0), "r"(b1));
}

// ---------------- prep: W2^T -> fp16, padded stride 136 ----------------
__global__ void prep_w2(const float* __restrict__ W2){
  int idx = blockIdx.x * blockDim.x + threadIdx.x;
  if (idx >= 4*128*128) return;
  int k = idx >> 14, rem = idx & 16383;
  int m = rem >> 7, c = rem & 127;
  g_W2h[(k*128 + m)*136 + c] = __float2half(W2[(k*128 + c)*128 + m]);
}

// ---------------- main ----------------
extern __shared__ __align__(16) char smc[];

__global__ __launch_bounds__(THREADS, 2)
void nri_mma_kernel(
    const float* __restrict__ inputs,    // [16,30,50,4]
    const float* __restrict__ rel_type,  // [16,870,4]
    const float* __restrict__ W1,        // [4,8,128]
    const float* __restrict__ b1,        // [4,128]
    const float* __restrict__ b2,        // [4,128]
    const float* __restrict__ oW1,       // [132,128]
    const float* __restrict__ ob1,
    const float* __restrict__ oW2,       // [128,128]
    const float* __restrict__ ob2,
    const float* __restrict__ oW3,       // [128,4]
    const float* __restrict__ ob3,
    float* __restrict__ out)             // [16,30,49,4]
{
  const int tid  = threadIdx.x;
  const int lane = tid & 31;
  const int g    = lane >> 2;      // groupID
  const int tg   = lane & 3;       // thread in group
  const int wid  = tid >> 5;
  const int wr   = wid >> 1;       // warp row (0..3): 32 edges
  const int wc   = wid & 1;        // warp col (0..1): 64 features
  const int b = blockIdx.x / TOUT;
  const int t = blockIdx.x % TOUT;

  const uint32_t sbase = smem_u32(smc);
  float* W1s  = (float*)(smc + SW1);
  float* b1s  = (float*)(smc + SB1);
  float* b2s  = (float*)(smc + SB2);
  float* RTk  = (float*)(smc + SRTK);
  float* AGG  = (float*)(smc + SAGG);
  float* XS   = (float*)(smc + SXS);
  float* ob1s = (float*)(smc + SOB);
  float* ob2s = (float*)(smc + SOB + 512);
  float* ob3s = (float*)(smc + SOB + 1024);

  // ---- prologue ----
  for (int i = tid; i < 1024; i += THREADS)          // W1 f32 (all k)
    cp16(sbase + SW1 + i*16, (const char*)W1 + i*16);
  for (int i = tid; i < 128; i += THREADS){
    cp16(sbase + SB1 + i*16, (const char*)b1 + i*16);
    cp16(sbase + SB2 + i*16, (const char*)b2 + i*16);
  }
  cp_commit();
  if (tid < 120){
    int n = tid >> 2, d = tid & 3;
    XS[tid] = inputs[((b*NN + n)*TFULL + t)*4 + d];
  }
  for (int i = tid; i < NN*128; i += THREADS) AGG[i] = 0.f;
  if (tid < 128) ob1s[tid] = ob1[tid];
  else           ob2s[tid-128] = ob2[tid-128];
  if (tid < 4) ob3s[tid] = ob3[tid];

  // ================= relation types (outer) =================
  for (int k = 0; k < 4; k++){
    // ---- stage W2k + rt_k ----
    for (int i = tid; i < 2176; i += THREADS)
      cp16(sbase + SW2 + i*16, (const char*)g_W2h + k*34816 + i*16);
    cp_commit();
    for (int i = tid; i < 896; i += THREADS)
      RTk[i] = (i < EDGES) ? rel_type[(b*EDGES + i)*4 + k] : 0.f;
    cp_wait0();
    __syncthreads();

    const float* w1k = W1s + k*1024;
    const float* b1k = b1s + k*128;
    const float* b2k = b2s + k*128;

    // ---- edge tiles ----
    for (int m = 0; m < NTILE; m++){
      // ---- layer 1 (f32x2) -> A fp16, rt folded ----
      {
        const int e1 = tid >> 1;
        const int c00 = (tid & 1) * 64;
        const int ge = m*128 + e1;
        float rte = 0.f;
        int n = 0, s = 0;
        if (ge < EDGES){
          n = (ge*565) >> 14;
          int idx = ge - n*29;
          s = idx + (idx >= n ? 1 : 0);
          rte = RTk[ge];
        }
        const float4 rv = *(const float4*)(XS + n*4);
        const float4 sv = *(const float4*)(XS + s*4);
        ull hp[8];
        hp[0]=pk2(rv.x,rv.x); hp[1]=pk2(rv.y,rv.y); hp[2]=pk2(rv.z,rv.z); hp[3]=pk2(rv.w,rv.w);
        hp[4]=pk2(sv.x,sv.x); hp[5]=pk2(sv.y,sv.y); hp[6]=pk2(sv.z,sv.z); hp[7]=pk2(sv.w,sv.w);
        char* Arow = smc + SA + e1*272;
        #pragma unroll
        for (int cc = 0; cc < 64; cc += 4){
          const int c = c00 + cc;
          const float4 b4 = *(const float4*)(b1k + c);
          ull a0 = pk2(b4.x, b4.y), a1 = pk2(b4.z, b4.w);
          #pragma unroll
          for (int i = 0; i < 8; i++){
            const float4 w = *(const float4*)(w1k + i*128 + c);
            ffma2(a0, hp[i], pk2(w.x, w.y));
            ffma2(a1, hp[i], pk2(w.z, w.w));
          }
          float v0,v1,v2,v3; upk2(v0,v1,a0); upk2(v2,v3,a1);
          __half2 h01 = __floats2half2_rn(fmaxf(v0,0.f)*rte, fmaxf(v1,0.f)*rte);
          __half2 h23 = __floats2half2_rn(fmaxf(v2,0.f)*rte, fmaxf(v3,0.f)*rte);
          uint2 st; st.x = *(uint32_t*)&h01; st.y = *(uint32_t*)&h23;
          *(uint2*)(Arow + c*2) = st;
        }
      }
      __syncthreads();

      // ---- z init = rt * b2 ----
      float z[2][8][4];
      {
        float rt2[4];
        #pragma unroll
        for (int i = 0; i < 2; i++)
          #pragma unroll
          for (int h = 0; h < 2; h++)
            rt2[i*2+h] = RTk[m*128 + wr*32 + i*16 + h*8 + g];
        #pragma unroll
        for (int j = 0; j < 8; j++){
          const float2 bp = *(const float2*)(b2k + wc*64 + j*8 + tg*2);
          #pragma unroll
          for (int i = 0; i < 2; i++){
            z[i][j][0] = rt2[i*2+0]*bp.x; z[i][j][1] = rt2[i*2+0]*bp.y;
            z[i][j][2] = rt2[i*2+1]*bp.x; z[i][j][3] = rt2[i*2+1]*bp.y;
          }
        }
      }
      // ---- mma mainloop: 8 k-steps of 16 ----
      {
        const char* Af = smc + SA  + (wr*32 + g)*272 + tg*4;
        const char* Bf = smc + SW2 + (wc*64 + g)*272 + tg*4;
        #pragma unroll
        for (int ks = 0; ks < 8; ks++){
          uint32_t a[2][4];
          #pragma unroll
          for (int i = 0; i < 2; i++){
            const char* ab = Af + i*(16*272) + ks*32;
            a[i][0] = *(const uint32_t*)(ab);
            a[i][1] = *(const uint32_t*)(ab + 8*272);
            a[i][2] = *(const uint32_t*)(ab + 16);
            a[i][3] = *(const uint32_t*)(ab + 8*272 + 16);
          }
          #pragma unroll
          for (int j = 0; j < 8; j++){
            const char* bb = Bf + j*(8*272) + ks*32;
            const uint32_t b0 = *(const uint32_t*)(bb);
            const uint32_t b1r = *(const uint32_t*)(bb + 16);
            mma16816(z[0][j], a[0][0],a[0][1],a[0][2],a[0][3], b0, b1r);
            mma16816(z[1][j], a[1][0],a[1][1],a[1][2],a[1][3], b0, b1r);
          }
        }
      }
      __syncthreads();   // all warps done reading A before msgs overwrite

      // ---- store msgs = relu(z) fp16 [128][132] (alias A) ----
      #pragma unroll
      for (int i = 0; i < 2; i++)
        #pragma unroll
        for (int h = 0; h < 2; h++){
          const int e = wr*32 + i*16 + h*8 + g;
          char* mrow = smc + SA + e*264;
          #pragma unroll
          for (int j = 0; j < 8; j++){
            const int f = wc*64 + j*8 + tg*2;
            __half2 hv = (h == 0)
              ? __floats2half2_rn(fmaxf(z[i][j][0],0.f), fmaxf(z[i][j][1],0.f))
              : __floats2half2_rn(fmaxf(z[i][j][2],0.f), fmaxf(z[i][j][3],0.f));
            *(uint32_t*)(mrow + f*2) = *(uint32_t*)&hv;
          }
        }
      __syncthreads();

      // ---- per-node partial sums -> AGG += ----
      {
        const __half* msgs = (const __half*)(smc + SA);
        const int f = tid & 127, h = tid >> 7;
        const int gbase = m*128;
        const int n0 = (gbase*565) >> 14;
        int n1 = ((gbase + 127)*565) >> 14;
        if (n1 > NN-1) n1 = NN-1;
        for (int nn = n0 + h; nn <= n1; nn += 2){
          int e0 = nn*29;        if (e0 < gbase) e0 = gbase;
          int e1e = nn*29 + 29;  if (e1e > gbase + 128) e1e = gbase + 128;
          float s = 0.f;
          for (int e = e0; e < e1e; e++)
            s += __half2float(msgs[(e - gbase)*132 + f]);
          AGG[nn*128 + f] += s;
        }
      }
      __syncthreads();
    }
  }

  // ================= node MLP (weight-stationary, i-split halves) =========
  float* AUG = (float*)(smc + PB_AUG);   // [30][132]
  float* H   = (float*)(smc + PB_H);     // [30][128]
  float* H2  = (float*)(smc + PB_H2);    // [30][129]
  float* P0  = (float*)(smc + PB_P0);
  float* P1  = (float*)(smc + PB_P1);

  for (int idx = tid; idx < NN*132; idx += THREADS){
    int n = idx / 132, i = idx - n*132;
    AUG[idx] = (i < 4) ? XS[n*4 + i] : AGG[n*128 + (i - 4)];
  }
  __syncthreads();
  { // layer 1: P[half] = aug @ oW1 (i-range split)
    const int f = tid & 127, half = tid >> 7;
    const int i0 = half ? 66 : 0, i1 = half ? 132 : 66;
    float acc[NN];
    #pragma unroll
    for (int n = 0; n < NN; n++) acc[n] = 0.f;
    for (int i = i0; i < i1; i++){
      const float w = oW1[i*128 + f];
      #pragma unroll
      for (int n = 0; n < NN; n++) acc[n] += AUG[n*132 + i] * w;
    }
    float* P = half ? P1 : P0;
    #pragma unroll
    for (int n = 0; n < NN; n++) P[n*128 + f] = acc[n];
  }
  __syncthreads();
  for (int idx = tid; idx < NN*128; idx += THREADS)
    H[idx] = fmaxf(P0[idx] + P1[idx] + ob1s[idx & 127], 0.f);
  __syncthreads();
  { // layer 2
    const int f = tid & 127, half = tid >> 7;
    const int i0 = half ? 64 : 0, i1 = half ? 128 : 64;
    float acc[NN];
    #pragma unroll
    for (int n = 0; n < NN; n++) acc[n] = 0.f;
    for (int i = i0; i < i1; i++){
      const float w = oW2[i*128 + f];
      #pragma unroll
      for (int n = 0; n < NN; n++) acc[n] += H[n*128 + i] * w;
    }
    float* P = half ? P1 : P0;
    #pragma unroll
    for (int n = 0; n < NN; n++) P[n*128 + f] = acc[n];
  }
  __syncthreads();
  for (int idx = tid; idx < NN*128; idx += THREADS){
    int n = idx >> 7, f = idx & 127;
    H2[n*129 + f] = fmaxf(P0[idx] + P1[idx] + ob2s[f], 0.f);
  }
  __syncthreads();
  if (tid < NN*4){ // layer 3 + residual
    const int n = tid >> 2, d = tid & 3;
    float a = ob3s[d];
    #pragma unroll 8
    for (int j = 0; j < 128; j++) a += H2[n*129 + j] * oW3[j*4 + d];
    out[((b*NN + n)*TOUT + t)*4 + d] = XS[n*4 + d] + a;
  }
}

extern "C" void kernel_launch(void* const* d_in, const int* in_sizes, int n_in,
                              void* d_out, int out_size) {
  (void)in_sizes; (void)n_in; (void)out_size;
  const float* inputs   = (const float*)d_in[0];
  const float* rel_type = (const float*)d_in[1];
  const float* W1  = (const float*)d_in[4];
  const float* b1  = (const float*)d_in[5];
  const float* W2  = (const float*)d_in[6];
  const float* b2  = (const float*)d_in[7];
  const float* oW1 = (const float*)d_in[8];
  const float* ob1 = (const float*)d_in[9];
  const float* oW2 = (const float*)d_in[10];
  const float* ob2 = (const float*)d_in[11];
  const float* oW3 = (const float*)d_in[12];
  const float* ob3 = (const float*)d_in[13];
  float* out = (float*)d_out;

  prep_w2<<<256, 256>>>(W2);

  cudaFuncSetAttribute(nri_mma_kernel,
                       cudaFuncAttributeMaxDynamicSharedMemorySize, SMEM_BYTES);
  nri_mma_kernel<<<GRID, THREADS, SMEM_BYTES>>>(
      inputs, rel_type, W1, b1, b2, oW1, ob1, oW2, ob2, oW3, ob3, out);
}

// round 10
// speedup vs baseline: 6.1411x; 1.7096x over previous
#include <cuda_runtime.h>
#include <cuda_fp16.h>
#include <cstdint>

// NRI MLPDecoder: layer-1 = mma.m16n8k8.tf32, layer-2 = mma.m16n8k16.f16 (ldmatrix),
// k-outer, 2 CTAs/SM. B=16,N=30,T=50(49 out),D=4,K=4,H=M=NH=128,E=870(pad 896).
// One CTA = one (b,t), 256 threads, grid 784.

typedef unsigned long long ull;

#define NB 16
#define NN 30
#define TFULL 50
#define TOUT 49
#define EDGES 870
#define NTILE 7
#define THREADS 256
#define GRID (NB*TOUT)

// ---------------- smem byte offsets ----------------
#define SA    0          // A fp16 [128][136] = 34816 (alias: msgs, same layout)
#define SW2   34816      // W2k fp16 [128][136] = 34816
#define SPRE  69632      // pre tf32 [128][12] = 6144
#define SW1K  75776      // W1k tf32 [8][136] = 4352
#define SB1   80128      // b1 f32 [4][128] = 2048
#define SB2   82176      // b2 f32 [4][128] = 2048
#define SRTK  84224      // rt_k f32 [896] = 3584
#define SAGG  87808      // agg f32 [30][128] = 15360 (region 15488 for H2 alias)
#define SXS   103296     // x f32 [32][4] = 512
#define SOB   103808     // ob1 512 + ob2 512 + ob3 16
#define SMEM_BYTES 104848

// phase-B aliases
#define PB_AUG  (SA)             // [30][132] f32
#define PB_H    (SA + 16384)     // [30][128] f32
#define PB_P0   (SW2)            // [30][128] f32
#define PB_P1   (SW2 + 16384)    // [30][128] f32
#define PB_H2   (SAGG)           // [30][129] f32 (needs 15488, fits region)

__device__ __align__(16) __half g_W2h[4*128*136];  // W2^T fp16: [k][m][c_pad136]

// ---------------- helpers ----------------
__device__ __forceinline__ uint32_t smem_u32(const void* p){
  uint32_t a; asm("{ .reg .u64 t; cvta.to.shared.u64 t, %1; cvt.u32.u64 %0, t; }" : "=r"(a) : "l"(p));
  return a;
}
__device__ __forceinline__ void cp16(uint32_t dst, const void* src){
  asm volatile("cp.async.ca.shared.global [%0], [%1], 16;" :: "r"(dst), "l"(src));
}
__device__ __forceinline__ void cp_commit(){ asm volatile("cp.async.commit_group;" ::: "memory"); }
__device__ __forceinline__ void cp_wait0(){ asm volatile("cp.async.wait_group 0;" ::: "memory"); }
__device__ __forceinline__ float cvt_tf32(float x){
  float o; asm("cvt.rna.tf32.f32 %0, %1;" : "=f"(o) : "f"(x)); return o;
}
__device__ __forceinline__ void mma16816(float* c,
    uint32_t a0, uint32_t a1, uint32_t a2, uint32_t a3,
    uint32_t b0, uint32_t b1){
  asm volatile("mma.sync.aligned.m16n8k16.row.col.f32.f16.f16.f32 "
    "{%0,%1,%2,%3}, {%4,%5,%6,%7}, {%8,%9}, {%0,%1,%2,%3};"
    : "+f"(c[0]), "+f"(c[1]), "+f"(c[2]), "+f"(c[3])
    : "r"(a0), "r"(a1), "r"(a2), "r"(a3), "r"(b0), "r"(b1));
}
__device__ __forceinline__ void mma_tf32(float* c,
    const uint32_t* a, uint32_t b0, uint32_t b1){
  asm volatile("mma.sync.aligned.m16n8k8.row.col.f32.tf32.tf32.f32 "
    "{%0,%1,%2,%3}, {%4,%5,%6,%7}, {%8,%9}, {%0,%1,%2,%3};"
    : "+f"(c[0]), "+f"(c[1]), "+f"(c[2]), "+f"(c[3])
    : "r"(a[0]), "r"(a[1]), "r"(a[2]), "r"(a[3]), "r"(b0), "r"(b1));
}
__device__ __forceinline__ void ldsm4(uint32_t* r, uint32_t addr){
  asm volatile("ldmatrix.sync.aligned.m8n8.x4.shared.b16 {%0,%1,%2,%3}, [%4];"
    : "=r"(r[0]), "=r"(r[1]), "=r"(r[2]), "=r"(r[3]) : "r"(addr));
}

// ---------------- prep: W2^T -> fp16, padded stride 136 ----------------
__global__ void prep_w2(const float* __restrict__ W2){
  int idx = blockIdx.x * blockDim.x + threadIdx.x;
  if (idx >= 4*128*128) return;
  int k = idx >> 14, rem = idx & 16383;
  int m = rem >> 7, c = rem & 127;
  g_W2h[(k*128 + m)*136 + c] = __float2half(W2[(k*128 + c)*128 + m]);
}

// ---------------- main ----------------
extern __shared__ __align__(16) char smc[];

__global__ __launch_bounds__(THREADS, 2)
void nri_mma_kernel(
    const float* __restrict__ inputs,    // [16,30,50,4]
    const float* __restrict__ rel_type,  // [16,870,4]
    const float* __restrict__ W1,        // [4,8,128]
    const float* __restrict__ b1,        // [4,128]
    const float* __restrict__ b2,        // [4,128]
    const float* __restrict__ oW1,       // [132,128]
    const float* __restrict__ ob1,
    const float* __restrict__ oW2,       // [128,128]
    const float* __restrict__ ob2,
    const float* __restrict__ oW3,       // [128,4]
    const float* __restrict__ ob3,
    float* __restrict__ out)             // [16,30,49,4]
{
  const int tid  = threadIdx.x;
  const int lane = tid & 31;
  const int g    = lane >> 2;      // groupID
  const int tg   = lane & 3;       // thread in group
  const int wid  = tid >> 5;
  const int wr   = wid >> 1;       // warp row (0..3): 32 edges
  const int wc   = wid & 1;        // warp col (0..1): 64 features
  const int b = blockIdx.x / TOUT;
  const int t = blockIdx.x % TOUT;

  const uint32_t sbase = smem_u32(smc);
  float* PREs = (float*)(smc + SPRE);
  float* W1Ks = (float*)(smc + SW1K);
  float* b1s  = (float*)(smc + SB1);
  float* b2s  = (float*)(smc + SB2);
  float* RTk  = (float*)(smc + SRTK);
  float* AGG  = (float*)(smc + SAGG);
  float* XS   = (float*)(smc + SXS);
  float* ob1s = (float*)(smc + SOB);
  float* ob2s = (float*)(smc + SOB + 512);
  float* ob3s = (float*)(smc + SOB + 1024);

  // ---- prologue ----
  for (int i = tid; i < 128; i += THREADS){
    cp16(sbase + SB1 + i*16, (const char*)b1 + i*16);
    cp16(sbase + SB2 + i*16, (const char*)b2 + i*16);
  }
  cp_commit();
  if (tid < 120){
    int n = tid >> 2, d = tid & 3;
    XS[tid] = inputs[((b*NN + n)*TFULL + t)*4 + d];
  }
  for (int i = tid; i < NN*128; i += THREADS) AGG[i] = 0.f;
  if (tid < 128) ob1s[tid] = ob1[tid];
  else           ob2s[tid-128] = ob2[tid-128];
  if (tid < 4) ob3s[tid] = ob3[tid];
  cp_wait0();

  // ================= relation types (outer) =================
  for (int k = 0; k < 4; k++){
    // ---- stage W2k (fp16), W1k (tf32), rt_k ----
    for (int i = tid; i < 2176; i += THREADS)
      cp16(sbase + SW2 + i*16, (const char*)g_W2h + k*34816 + i*16);
    cp_commit();
    for (int i = tid; i < 1024; i += THREADS)
      W1Ks[(i >> 7)*136 + (i & 127)] = cvt_tf32(W1[k*1024 + i]);
    for (int i = tid; i < 896; i += THREADS)
      RTk[i] = (i < EDGES) ? rel_type[(b*EDGES + i)*4 + k] : 0.f;
    cp_wait0();
    __syncthreads();

    const float* b1k = b1s + k*128;
    const float* b2k = b2s + k*128;

    // ---- edge tiles ----
    for (int m = 0; m < NTILE; m++){
      // ---- build pre (tf32) [128][12]: [x_recv | x_send] ----
      {
        const int e1 = tid >> 1, half = tid & 1;
        const int ge = m*128 + e1;
        float4 v = make_float4(0.f, 0.f, 0.f, 0.f);
        if (ge < EDGES){
          int n = (ge*565) >> 14;
          int idx = ge - n*29;
          int s = idx + (idx >= n ? 1 : 0);
          v = *(const float4*)(XS + (half ? s : n)*4);
        }
        float4 o = make_float4(cvt_tf32(v.x), cvt_tf32(v.y), cvt_tf32(v.z), cvt_tf32(v.w));
        *(float4*)(PREs + e1*12 + half*4) = o;
      }
      __syncthreads();   // PRE ready; also: prev-tile agg readers done before A overwrite

      // ---- layer 1: tf32 MMA -> relu(+b1)*rt -> A fp16 ----
      {
        uint32_t za[2][4];
        const uint32_t* PB = (const uint32_t*)PREs;
        #pragma unroll
        for (int i = 0; i < 2; i++){
          const int r0 = wr*32 + i*16;
          za[i][0] = PB[(r0 + g)*12 + tg];
          za[i][1] = PB[(r0 + 8 + g)*12 + tg];
          za[i][2] = PB[(r0 + g)*12 + tg + 4];
          za[i][3] = PB[(r0 + 8 + g)*12 + tg + 4];
        }
        float z1[2][8][4];
        #pragma unroll
        for (int i = 0; i < 2; i++)
          #pragma unroll
          for (int j = 0; j < 8; j++)
            #pragma unroll
            for (int r = 0; r < 4; r++) z1[i][j][r] = 0.f;
        const uint32_t* WB = (const uint32_t*)W1Ks;
        #pragma unroll
        for (int j = 0; j < 8; j++){
          const int col = wc*64 + j*8 + g;
          const uint32_t b0 = WB[tg*136 + col];
          const uint32_t b1r = WB[(tg + 4)*136 + col];
          mma_tf32(z1[0][j], za[0], b0, b1r);
          mma_tf32(z1[1][j], za[1], b0, b1r);
        }
        #pragma unroll
        for (int i = 0; i < 2; i++){
          const int elo = wr*32 + i*16 + g, ehi = elo + 8;
          const float rlo = RTk[m*128 + elo], rhi = RTk[m*128 + ehi];
          #pragma unroll
          for (int j = 0; j < 8; j++){
            const int colb = wc*64 + j*8 + tg*2;
            const float2 bp = *(const float2*)(b1k + colb);
            __half2 hlo = __floats2half2_rn(fmaxf(z1[i][j][0] + bp.x, 0.f)*rlo,
                                            fmaxf(z1[i][j][1] + bp.y, 0.f)*rlo);
            __half2 hhi = __floats2half2_rn(fmaxf(z1[i][j][2] + bp.x, 0.f)*rhi,
                                            fmaxf(z1[i][j][3] + bp.y, 0.f)*rhi);
            *(uint32_t*)(smc + SA + elo*272 + colb*2) = *(uint32_t*)&hlo;
            *(uint32_t*)(smc + SA + ehi*272 + colb*2) = *(uint32_t*)&hhi;
          }
        }
      }
      __syncthreads();   // A ready

      // ---- layer 2: z init = rt*b2; mma mainloop with ldmatrix ----
      float z[2][8][4];
      {
        float rt2[4];
        #pragma unroll
        for (int i = 0; i < 2; i++)
          #pragma unroll
          for (int h = 0; h < 2; h++)
            rt2[i*2+h] = RTk[m*128 + wr*32 + i*16 + h*8 + g];
        #pragma unroll
        for (int j = 0; j < 8; j++){
          const float2 bp = *(const float2*)(b2k + wc*64 + j*8 + tg*2);
          #pragma unroll
          for (int i = 0; i < 2; i++){
            z[i][j][0] = rt2[i*2+0]*bp.x; z[i][j][1] = rt2[i*2+0]*bp.y;
            z[i][j][2] = rt2[i*2+1]*bp.x; z[i][j][3] = rt2[i*2+1]*bp.y;
          }
        }
      }
      {
        const int r = lane & 7, q = lane >> 3;
        uint32_t aA[2], bA[4];
        #pragma unroll
        for (int i = 0; i < 2; i++)
          aA[i] = sbase + SA + (wr*32 + i*16 + (q & 1)*8 + r)*272 + (q >> 1)*16;
        #pragma unroll
        for (int jp = 0; jp < 4; jp++)
          bA[jp] = sbase + SW2 + (wc*64 + (jp*2 + (q >> 1))*8 + r)*272 + (q & 1)*16;
        #pragma unroll
        for (int ks = 0; ks < 8; ks++){
          uint32_t a0[4], a1[4], bq[4][4];
          ldsm4(a0, aA[0] + ks*32);
          ldsm4(a1, aA[1] + ks*32);
          #pragma unroll
          for (int jp = 0; jp < 4; jp++) ldsm4(bq[jp], bA[jp] + ks*32);
          #pragma unroll
          for (int jp = 0; jp < 4; jp++){
            mma16816(z[0][2*jp],   a0[0],a0[1],a0[2],a0[3], bq[jp][0], bq[jp][1]);
            mma16816(z[1][2*jp],   a1[0],a1[1],a1[2],a1[3], bq[jp][0], bq[jp][1]);
            mma16816(z[0][2*jp+1], a0[0],a0[1],a0[2],a0[3], bq[jp][2], bq[jp][3]);
            mma16816(z[1][2*jp+1], a1[0],a1[1],a1[2],a1[3], bq[jp][2], bq[jp][3]);
          }
        }
      }
      __syncthreads();   // all reads of A done before msgs overwrite

      // ---- store msgs = relu(z) fp16 [128][136] (alias A) ----
      #pragma unroll
      for (int i = 0; i < 2; i++){
        const int elo = wr*32 + i*16 + g, ehi = elo + 8;
        #pragma unroll
        for (int j = 0; j < 8; j++){
          const int f = wc*64 + j*8 + tg*2;
          __half2 hlo = __floats2half2_rn(fmaxf(z[i][j][0],0.f), fmaxf(z[i][j][1],0.f));
          __half2 hhi = __floats2half2_rn(fmaxf(z[i][j][2],0.f), fmaxf(z[i][j][3],0.f));
          *(uint32_t*)(smc + SA + elo*272 + f*2) = *(uint32_t*)&hlo;
          *(uint32_t*)(smc + SA + ehi*272 + f*2) = *(uint32_t*)&hhi;
        }
      }
      __syncthreads();   // msgs ready

      // ---- per-node partial sums -> AGG += (all 256 threads, half2) ----
      {
        const __half* msgs = (const __half*)(smc + SA);
        const int fp = tid & 63, grp = tid >> 6;
        const int gbase = m*128;
        const int n0 = (gbase*565) >> 14;
        int n1 = ((gbase + 127)*565) >> 14;
        if (n1 > NN-1) n1 = NN-1;
        for (int nn = n0 + grp; nn <= n1; nn += 4){
          int e0 = nn*29;        if (e0 < gbase) e0 = gbase;
          int e1e = nn*29 + 29;  if (e1e > gbase + 128) e1e = gbase + 128;
          float sx = 0.f, sy = 0.f;
          for (int e = e0; e < e1e; e++){
            const __half2 hv = *(const __half2*)(msgs + (e - gbase)*136 + fp*2);
            const float2 f2 = __half22float2(hv);
            sx += f2.x; sy += f2.y;
          }
          float2* ap = (float2*)(AGG + nn*128 + fp*2);
          float2 cur = *ap; cur.x += sx; cur.y += sy; *ap = cur;
        }
      }
      // no trailing sync: next iter's PRE build is disjoint; sync after PRE covers
    }
    __syncthreads();   // before restaging W2/W1K/RTk
  }

  // ================= node MLP (weight-stationary, i-split halves) =========
  float* AUG = (float*)(smc + PB_AUG);   // [30][132]
  float* H   = (float*)(smc + PB_H);     // [30][128]
  float* H2  = (float*)(smc + PB_H2);    // [30][129]
  float* P0  = (float*)(smc + PB_P0);
  float* P1  = (float*)(smc + PB_P1);

  for (int idx = tid; idx < NN*132; idx += THREADS){
    int n = idx / 132, i = idx - n*132;
    AUG[idx] = (i < 4) ? XS[n*4 + i] : AGG[n*128 + (i - 4)];
  }
  __syncthreads();
  { // layer 1: P[half] = aug @ oW1 (i-range split)
    const int f = tid & 127, half = tid >> 7;
    const int i0 = half ? 66 : 0, i1 = half ? 132 : 66;
    float acc[NN];
    #pragma unroll
    for (int n = 0; n < NN; n++) acc[n] = 0.f;
    for (int i = i0; i < i1; i++){
      const float w = oW1[i*128 + f];
      #pragma unroll
      for (int n = 0; n < NN; n++) acc[n] += AUG[n*132 + i] * w;
    }
    float* P = half ? P1 : P0;
    #pragma unroll
    for (int n = 0; n < NN; n++) P[n*128 + f] = acc[n];
  }
  __syncthreads();
  for (int idx = tid; idx < NN*128; idx += THREADS)
    H[idx] = fmaxf(P0[idx] + P1[idx] + ob1s[idx & 127], 0.f);
  __syncthreads();
  { // layer 2
    const int f = tid & 127, half = tid >> 7;
    const int i0 = half ? 64 : 0, i1 = half ? 128 : 64;
    float acc[NN];
    #pragma unroll
    for (int n = 0; n < NN; n++) acc[n] = 0.f;
    for (int i = i0; i < i1; i++){
      const float w = oW2[i*128 + f];
      #pragma unroll
      for (int n = 0; n < NN; n++) acc[n] += H[n*128 + i] * w;
    }
    float* P = half ? P1 : P0;
    #pragma unroll
    for (int n = 0; n < NN; n++) P[n*128 + f] = acc[n];
  }
  __syncthreads();
  for (int idx = tid; idx < NN*128; idx += THREADS){
    int n = idx >> 7, f = idx & 127;
    H2[n*129 + f] = fmaxf(P0[idx] + P1[idx] + ob2s[f], 0.f);
  }
  __syncthreads();
  if (tid < NN*4){ // layer 3 + residual
    const int n = tid >> 2, d = tid & 3;
    float a = ob3s[d];
    #pragma unroll 8
    for (int j = 0; j < 128; j++) a += H2[n*129 + j] * oW3[j*4 + d];
    out[((b*NN + n)*TOUT + t)*4 + d] = XS[n*4 + d] + a;
  }
}

extern "C" void kernel_launch(void* const* d_in, const int* in_sizes, int n_in,
                              void* d_out, int out_size) {
  (void)in_sizes; (void)n_in; (void)out_size;
  const float* inputs   = (const float*)d_in[0];
  const float* rel_type = (const float*)d_in[1];
  const float* W1  = (const float*)d_in[4];
  const float* b1  = (const float*)d_in[5];
  const float* W2  = (const float*)d_in[6];
  const float* b2  = (const float*)d_in[7];
  const float* oW1 = (const float*)d_in[8];
  const float* ob1 = (const float*)d_in[9];
  const float* oW2 = (const float*)d_in[10];
  const float* ob2 = (const float*)d_in[11];
  const float* oW3 = (const float*)d_in[12];
  const float* ob3 = (const float*)d_in[13];
  float* out = (float*)d_out;

  prep_w2<<<256, 256>>>(W2);

  cudaFuncSetAttribute(nri_mma_kernel,
                       cudaFuncAttributeMaxDynamicSharedMemorySize, SMEM_BYTES);
  nri_mma_kernel<<<GRID, THREADS, SMEM_BYTES>>>(
      inputs, rel_type, W1, b1, b2, oW1, ob1, oW2, ob2, oW3, ob3, out);
}

// round 11
// speedup vs baseline: 6.3213x; 1.0293x over previous
#include <cuda_runtime.h>
#include <cuda_fp16.h>
#include <cstdint>

// NRI MLPDecoder: L1 = mma.m16n8k8.tf32 (C-frag == L2 A-frag, in-register),
// L2 = mma.m16n8k16.f16 (ldmatrix B), aggregation = HMMA with R matrix
// (rel_type folded into R). k-outer, 2 CTAs/SM.
// B=16,N=30,T=50(49 out),D=4,K=4,H=M=NH=128,E=870(pad 896 = 7x128).
// One CTA = one (b,t), 256 threads, grid 784. Warp w owns edge rows w*16..w*16+15.

typedef unsigned long long ull;

#define NB 16
#define NN 30
#define TFULL 50
#define TOUT 49
#define EDGES 870
#define NTILE 7
#define THREADS 256
#define GRID (NB*TOUT)

// ---------------- smem byte offsets ----------------
#define SA    0          // msgs fp16 [128][136] = 34816
#define SW2   34816      // W2k fp16 [128][136] = 34816
#define SPRE  69632      // pre tf32 [128][12] = 6144
#define SW1K  75776      // W1k tf32 [8][136] = 4352
#define SB1   80128      // b1 f32 [4][128] = 2048
#define SB2   82176      // b2 f32 [4][128] = 2048
#define SRTK  84224      // rt_k f32 [896] = 3584
#define SR    87808      // R fp16 [16][136] = 4352
#define SAGG  92160      // agg f32 [30][132] = 15840 (stride 132: conflict relief)
#define SXS   108000     // x f32 [32][4] = 512
#define SOB   108512     // ob1 512 + ob2 512 + ob3 16
#define SMEM_BYTES 109552

// phase-B aliases
#define PB_AUG  (SA)             // [30][132] f32
#define PB_H    (SA + 16384)     // [30][128] f32
#define PB_P0   (SW2)            // [30][128] f32
#define PB_P1   (SW2 + 16384)    // [30][128] f32
#define PB_H2   (SAGG)           // [30][129] f32 (15480 <= 15840)

__device__ __align__(16) __half g_W2h[4*128*136];  // W2^T fp16: [k][f][c_pad136]

// ---------------- helpers ----------------
__device__ __forceinline__ uint32_t smem_u32(const void* p){
  uint32_t a; asm("{ .reg .u64 t; cvta.to.shared.u64 t, %1; cvt.u32.u64 %0, t; }" : "=r"(a) : "l"(p));
  return a;
}
__device__ __forceinline__ void cp16(uint32_t dst, const void* src){
  asm volatile("cp.async.ca.shared.global [%0], [%1], 16;" :: "r"(dst), "l"(src));
}
__device__ __forceinline__ void cp_commit(){ asm volatile("cp.async.commit_group;" ::: "memory"); }
__device__ __forceinline__ void cp_wait0(){ asm volatile("cp.async.wait_group 0;" ::: "memory"); }
__device__ __forceinline__ float cvt_tf32(float x){
  float o; asm("cvt.rna.tf32.f32 %0, %1;" : "=f"(o) : "f"(x)); return o;
}
__device__ __forceinline__ void mma16816(float* c,
    uint32_t a0, uint32_t a1, uint32_t a2, uint32_t a3,
    uint32_t b0, uint32_t b1){
  asm volatile("mma.sync.aligned.m16n8k16.row.col.f32.f16.f16.f32 "
    "{%0,%1,%2,%3}, {%4,%5,%6,%7}, {%8,%9}, {%0,%1,%2,%3};"
    : "+f"(c[0]), "+f"(c[1]), "+f"(c[2]), "+f"(c[3])
    : "r"(a0), "r"(a1), "r"(a2), "r"(a3), "r"(b0), "r"(b1));
}
__device__ __forceinline__ void mma_tf32(float* c,
    const uint32_t* a, uint32_t b0, uint32_t b1){
  asm volatile("mma.sync.aligned.m16n8k8.row.col.f32.tf32.tf32.f32 "
    "{%0,%1,%2,%3}, {%4,%5,%6,%7}, {%8,%9}, {%0,%1,%2,%3};"
    : "+f"(c[0]), "+f"(c[1]), "+f"(c[2]), "+f"(c[3])
    : "r"(a[0]), "r"(a[1]), "r"(a[2]), "r"(a[3]), "r"(b0), "r"(b1));
}
__device__ __forceinline__ void ldsm4(uint32_t* r, uint32_t addr){
  asm volatile("ldmatrix.sync.aligned.m8n8.x4.shared.b16 {%0,%1,%2,%3}, [%4];"
    : "=r"(r[0]), "=r"(r[1]), "=r"(r[2]), "=r"(r[3]) : "r"(addr));
}
__device__ __forceinline__ void ldsm4t(uint32_t* r, uint32_t addr){
  asm volatile("ldmatrix.sync.aligned.m8n8.x4.trans.shared.b16 {%0,%1,%2,%3}, [%4];"
    : "=r"(r[0]), "=r"(r[1]), "=r"(r[2]), "=r"(r[3]) : "r"(addr));
}
__device__ __forceinline__ uint32_t relu_pack(float a, float b){
  __half2 h = __floats2half2_rn(a, b);
  __half2 z = __half2half2(__ushort_as_half(0));
  __half2 r = __hmax2(h, z);
  return *(uint32_t*)&r;
}

// ---------------- prep: W2^T -> fp16, padded stride 136 ----------------
__global__ void prep_w2(const float* __restrict__ W2){
  int idx = blockIdx.x * blockDim.x + threadIdx.x;
  if (idx >= 4*128*128) return;
  int k = idx >> 14, rem = idx & 16383;
  int m = rem >> 7, c = rem & 127;
  g_W2h[(k*128 + m)*136 + c] = __float2half(W2[(k*128 + c)*128 + m]);
}

// ---------------- main ----------------
extern __shared__ __align__(16) char smc[];

__global__ __launch_bounds__(THREADS, 2)
void nri_mma_kernel(
    const float* __restrict__ inputs,    // [16,30,50,4]
    const float* __restrict__ rel_type,  // [16,870,4]
    const float* __restrict__ W1,        // [4,8,128]
    const float* __restrict__ b1,        // [4,128]
    const float* __restrict__ b2,        // [4,128]
    const float* __restrict__ oW1,       // [132,128]
    const float* __restrict__ ob1,
    const float* __restrict__ oW2,       // [128,128]
    const float* __restrict__ ob2,
    const float* __restrict__ oW3,       // [128,4]
    const float* __restrict__ ob3,
    float* __restrict__ out)             // [16,30,49,4]
{
  const int tid  = threadIdx.x;
  const int lane = tid & 31;
  const int g    = lane >> 2;      // groupID
  const int tg   = lane & 3;       // thread in group
  const int wid  = tid >> 5;       // warp: rows wid*16..wid*16+15 / feat slice wid*16
  const int qq   = lane >> 3;      // ldmatrix quad
  const int rr   = lane & 7;
  const int b = blockIdx.x / TOUT;
  const int t = blockIdx.x % TOUT;

  const uint32_t sbase = smem_u32(smc);
  float* PREs = (float*)(smc + SPRE);
  float* W1Ks = (float*)(smc + SW1K);
  float* b1s  = (float*)(smc + SB1);
  float* b2s  = (float*)(smc + SB2);
  float* RTk  = (float*)(smc + SRTK);
  float* AGG  = (float*)(smc + SAGG);
  float* XS   = (float*)(smc + SXS);
  float* ob1s = (float*)(smc + SOB);
  float* ob2s = (float*)(smc + SOB + 512);
  float* ob3s = (float*)(smc + SOB + 1024);

  // ---- prologue ----
  for (int i = tid; i < 128; i += THREADS){
    cp16(sbase + SB1 + i*16, (const char*)b1 + i*16);
    cp16(sbase + SB2 + i*16, (const char*)b2 + i*16);
  }
  cp_commit();
  if (tid < 120){
    int n = tid >> 2, d = tid & 3;
    XS[tid] = inputs[((b*NN + n)*TFULL + t)*4 + d];
  }
  for (int i = tid; i < NN*132; i += THREADS) AGG[i] = 0.f;
  if (tid < 128) ob1s[tid] = ob1[tid];
  else           ob2s[tid-128] = ob2[tid-128];
  if (tid < 4) ob3s[tid] = ob3[tid];
  cp_wait0();

  // ================= relation types (outer) =================
  for (int k = 0; k < 4; k++){
    // ---- stage W2k (fp16), W1k (tf32), rt_k ----
    for (int i = tid; i < 2176; i += THREADS)
      cp16(sbase + SW2 + i*16, (const char*)g_W2h + k*34816 + i*16);
    cp_commit();
    for (int i = tid; i < 1024; i += THREADS)
      W1Ks[(i >> 7)*136 + (i & 127)] = cvt_tf32(W1[k*1024 + i]);
    for (int i = tid; i < 896; i += THREADS)
      RTk[i] = (i < EDGES) ? rel_type[(b*EDGES + i)*4 + k] : 0.f;
    cp_wait0();
    __syncthreads();

    const float* b1k = b1s + k*128;
    const float* b2k = b2s + k*128;

    // ---- edge tiles ----
    for (int m = 0; m < NTILE; m++){
      const int gbase = m*128;
      const int n0 = (gbase*565) >> 14;

      // ---- build pre (tf32) [128][12] + R fp16 [16][136] ----
      {
        const int e1 = tid >> 1, half = tid & 1;
        const int ge = gbase + e1;
        float4 v = make_float4(0.f, 0.f, 0.f, 0.f);
        if (ge < EDGES){
          int n = (ge*565) >> 14;
          int idx = ge - n*29;
          int s = idx + (idx >= n ? 1 : 0);
          v = *(const float4*)(XS + (half ? s : n)*4);
        }
        *(float4*)(PREs + e1*12 + half*4) =
          make_float4(cvt_tf32(v.x), cvt_tf32(v.y), cvt_tf32(v.z), cvt_tf32(v.w));
        // R: rt folded; pad edges have rt=0
        #pragma unroll
        for (int it = 0; it < 4; it++){
          const int idx = tid + it*256;        // 1024 half2 entries
          const int row = idx >> 6, pr = idx & 63;
          const int e = pr*2, geA = gbase + e;
          const int nA = (geA*565) >> 14, nB = ((geA+1)*565) >> 14;
          const float vA = (nA == n0 + row) ? RTk[geA] : 0.f;
          const float vB = (nB == n0 + row) ? RTk[geA+1] : 0.f;
          *(__half2*)(smc + SR + row*272 + e*2) = __floats2half2_rn(vA, vB);
        }
      }
      __syncthreads();   // s1: PRE+R ready (also: prev agg done via s3)

      // ---- layer 1: tf32 MMA -> relu -> A-frags in registers ----
      uint32_t af[8][4];
      {
        const int r0 = wid*16;
        uint32_t za[4];
        const uint32_t* PB = (const uint32_t*)PREs;
        za[0] = PB[(r0 + g)*12 + tg];
        za[1] = PB[(r0 + 8 + g)*12 + tg];
        za[2] = PB[(r0 + g)*12 + tg + 4];
        za[3] = PB[(r0 + 8 + g)*12 + tg + 4];
        const uint32_t* WB = (const uint32_t*)W1Ks;
        #pragma unroll
        for (int ks = 0; ks < 8; ks++){
          float za1[4], zb1[4];
          {
            const float2 bpA = *(const float2*)(b1k + (2*ks)*8 + tg*2);
            const float2 bpB = *(const float2*)(b1k + (2*ks+1)*8 + tg*2);
            za1[0]=bpA.x; za1[1]=bpA.y; za1[2]=bpA.x; za1[3]=bpA.y;
            zb1[0]=bpB.x; zb1[1]=bpB.y; zb1[2]=bpB.x; zb1[3]=bpB.y;
          }
          {
            const int colA = (2*ks)*8 + g, colB = (2*ks+1)*8 + g;
            mma_tf32(za1, za, WB[tg*136 + colA], WB[(tg+4)*136 + colA]);
            mma_tf32(zb1, za, WB[tg*136 + colB], WB[(tg+4)*136 + colB]);
          }
          af[ks][0] = relu_pack(za1[0], za1[1]);
          af[ks][1] = relu_pack(za1[2], za1[3]);
          af[ks][2] = relu_pack(zb1[0], zb1[1]);
          af[ks][3] = relu_pack(zb1[2], zb1[3]);
        }
      }

      // ---- layer 2: two N-halves; msgs = relu(z + b2) -> SA ----
      const int rlo = wid*16 + g, rhi = rlo + 8;
      #pragma unroll
      for (int h2 = 0; h2 < 2; h2++){
        const int fb = h2*64;
        float z[8][4];
        #pragma unroll
        for (int j = 0; j < 8; j++){
          const float2 bp = *(const float2*)(b2k + fb + j*8 + tg*2);
          z[j][0]=bp.x; z[j][1]=bp.y; z[j][2]=bp.x; z[j][3]=bp.y;
        }
        #pragma unroll
        for (int ks = 0; ks < 8; ks++){
          uint32_t bq[4][4];
          #pragma unroll
          for (int jp = 0; jp < 4; jp++)
            ldsm4(bq[jp], sbase + SW2 +
              ((h2*8 + jp*2 + (qq >> 1))*8 + rr)*272 + (qq & 1)*16 + ks*32);
          #pragma unroll
          for (int jp = 0; jp < 4; jp++){
            mma16816(z[2*jp],   af[ks][0],af[ks][1],af[ks][2],af[ks][3], bq[jp][0], bq[jp][1]);
            mma16816(z[2*jp+1], af[ks][0],af[ks][1],af[ks][2],af[ks][3], bq[jp][2], bq[jp][3]);
          }
        }
        #pragma unroll
        for (int j = 0; j < 8; j++){
          const int f = fb + j*8 + tg*2;
          *(uint32_t*)(smc + SA + rlo*272 + f*2) = relu_pack(z[j][0], z[j][1]);
          *(uint32_t*)(smc + SA + rhi*272 + f*2) = relu_pack(z[j][2], z[j][3]);
        }
      }
      __syncthreads();   // s2: all msgs visible

      // ---- aggregation MMA: C[16 nodes][16 feat] = R @ msgs ----
      {
        const int f0 = wid*16;
        float cagg[2][4];
        #pragma unroll
        for (int j = 0; j < 2; j++)
          #pragma unroll
          for (int r2 = 0; r2 < 4; r2++) cagg[j][r2] = 0.f;
        const uint32_t Ra = sbase + SR + ((qq & 1)*8 + rr)*272 + (qq >> 1)*16;
        const uint32_t Ba = sbase + SA + ((qq & 1)*8 + rr)*272 + (f0 + (qq >> 1)*8)*2;
        #pragma unroll
        for (int ks = 0; ks < 8; ks++){
          uint32_t ar[4], br[4];
          ldsm4(ar, Ra + ks*32);
          ldsm4t(br, Ba + ks*16*272);
          mma16816(cagg[0], ar[0],ar[1],ar[2],ar[3], br[0], br[1]);
          mma16816(cagg[1], ar[0],ar[1],ar[2],ar[3], br[2], br[3]);
        }
        const int row0 = n0 + g, row1 = n0 + 8 + g;
        if (row0 < NN){
          #pragma unroll
          for (int j = 0; j < 2; j++){
            float2* p = (float2*)(AGG + row0*132 + f0 + j*8 + tg*2);
            float2 c = *p; c.x += cagg[j][0]; c.y += cagg[j][1]; *p = c;
          }
        }
        if (row1 < NN){
          #pragma unroll
          for (int j = 0; j < 2; j++){
            float2* p = (float2*)(AGG + row1*132 + f0 + j*8 + tg*2);
            float2 c = *p; c.x += cagg[j][2]; c.y += cagg[j][3]; *p = c;
          }
        }
      }
      __syncthreads();   // s3: agg done before PRE/R/msgs overwrite
    }
  }

  // ================= node MLP (weight-stationary, i-split halves) =========
  float* AUG = (float*)(smc + PB_AUG);   // [30][132]
  float* H   = (float*)(smc + PB_H);     // [30][128]
  float* H2  = (float*)(smc + PB_H2);    // [30][129]
  float* P0  = (float*)(smc + PB_P0);
  float* P1  = (float*)(smc + PB_P1);

  for (int idx = tid; idx < NN*132; idx += THREADS){
    int n = idx / 132, i = idx - n*132;
    AUG[idx] = (i < 4) ? XS[n*4 + i] : AGG[n*132 + (i - 4)];
  }
  __syncthreads();
  { // layer 1: P[half] = aug @ oW1 (i-range split)
    const int f = tid & 127, half = tid >> 7;
    const int i0 = half ? 66 : 0, i1 = half ? 132 : 66;
    float acc[NN];
    #pragma unroll
    for (int n = 0; n < NN; n++) acc[n] = 0.f;
    for (int i = i0; i < i1; i++){
      const float w = oW1[i*128 + f];
      #pragma unroll
      for (int n = 0; n < NN; n++) acc[n] += AUG[n*132 + i] * w;
    }
    float* P = half ? P1 : P0;
    #pragma unroll
    for (int n = 0; n < NN; n++) P[n*128 + f] = acc[n];
  }
  __syncthreads();
  for (int idx = tid; idx < NN*128; idx += THREADS)
    H[idx] = fmaxf(P0[idx] + P1[idx] + ob1s[idx & 127], 0.f);
  __syncthreads();
  { // layer 2
    const int f = tid & 127, half = tid >> 7;
    const int i0 = half ? 64 : 0, i1 = half ? 128 : 64;
    float acc[NN];
    #pragma unroll
    for (int n = 0; n < NN; n++) acc[n] = 0.f;
    for (int i = i0; i < i1; i++){
      const float w = oW2[i*128 + f];
      #pragma unroll
      for (int n = 0; n < NN; n++) acc[n] += H[n*128 + i] * w;
    }
    float* P = half ? P1 : P0;
    #pragma unroll
    for (int n = 0; n < NN; n++) P[n*128 + f] = acc[n];
  }
  __syncthreads();
  for (int idx = tid; idx < NN*128; idx += THREADS){
    int n = idx >> 7, f = idx & 127;
    H2[n*129 + f] = fmaxf(P0[idx] + P1[idx] + ob2s[f], 0.f);
  }
  __syncthreads();
  if (tid < NN*4){ // layer 3 + residual
    const int n = tid >> 2, d = tid & 3;
    float a = ob3s[d];
    #pragma unroll 8
    for (int j = 0; j < 128; j++) a += H2[n*129 + j] * oW3[j*4 + d];
    out[((b*NN + n)*TOUT + t)*4 + d] = XS[n*4 + d] + a;
  }
}

extern "C" void kernel_launch(void* const* d_in, const int* in_sizes, int n_in,
                              void* d_out, int out_size) {
  (void)in_sizes; (void)n_in; (void)out_size;
  const float* inputs   = (const float*)d_in[0];
  const float* rel_type = (const float*)d_in[1];
  const float* W1  = (const float*)d_in[4];
  const float* b1  = (const float*)d_in[5];
  const float* W2  = (const float*)d_in[6];
  const float* b2  = (const float*)d_in[7];
  const float* oW1 = (const float*)d_in[8];
  const float* ob1 = (const float*)d_in[9];
  const float* oW2 = (const float*)d_in[10];
  const float* ob2 = (const float*)d_in[11];
  const float* oW3 = (const float*)d_in[12];
  const float* ob3 = (const float*)d_in[13];
  float* out = (float*)d_out;

  prep_w2<<<256, 256>>>(W2);

  cudaFuncSetAttribute(nri_mma_kernel,
                       cudaFuncAttributeMaxDynamicSharedMemorySize, SMEM_BYTES);
  nri_mma_kernel<<<GRID, THREADS, SMEM_BYTES>>>(
      inputs, rel_type, W1, b1, b2, oW1, ob1, oW2, ob2, oW3, ob3, out);
}